// round 4
// baseline (speedup 1.0000x reference)
#include <cuda_runtime.h>
#include <cstdint>

#define N_ROWS 8192
#define D_IN   1024
#define D_OUT  4096
#define GAMMA  0.01618f
#define NEG_SLOPE 0.01f
#define TOPC   128

// GEMM tile config
#define BM 128
#define BN 256
#define BK 32
#define PAD_A 132
#define PAD_B 260
#define SMEM_FLOATS (2 * BK * PAD_A + 2 * BK * PAD_B)   // 8448 + 16640 = 25088
#define SMEM_BYTES  (SMEM_FLOATS * 4)                    // 100352

// Scratch: device globals (allocation-free per harness rules)
__device__ float g_h[(size_t)N_ROWS * D_OUT];      // 128 MB activations
__device__ uint2 g_cand[(size_t)N_ROWS * TOPC];    // 8 MB: (float bits, idx), sorted desc

// ---------------------------------------------------------------------------
// Zero-fill output
// ---------------------------------------------------------------------------
__global__ void fill_kernel(float4* __restrict__ out, int n4) {
    int i = blockIdx.x * blockDim.x + threadIdx.x;
    if (i < n4) out[i] = make_float4(0.f, 0.f, 0.f, 0.f);
}

// ---------------------------------------------------------------------------
// Packed fp32x2 helpers (sm_103a FFMA2 path — PTX only)
// ---------------------------------------------------------------------------
__device__ __forceinline__ unsigned long long ffma2(unsigned long long a,
                                                    unsigned long long b,
                                                    unsigned long long c) {
    unsigned long long d;
    asm("fma.rn.f32x2 %0, %1, %2, %3;" : "=l"(d) : "l"(a), "l"(b), "l"(c));
    return d;
}
__device__ __forceinline__ unsigned long long dupf(float x) {
    unsigned long long d;
    unsigned u = __float_as_uint(x);
    asm("mov.b64 %0, {%1, %1};" : "=l"(d) : "r"(u));
    return d;
}
__device__ __forceinline__ void unpack2(unsigned long long p, float& lo, float& hi) {
    unsigned a, b;
    asm("mov.b64 {%0, %1}, %2;" : "=r"(a), "=r"(b) : "l"(p));
    lo = __uint_as_float(a);
    hi = __uint_as_float(b);
}

// ---------------------------------------------------------------------------
// Phase 1a: fp32 GEMM via FFMA2  h = leaky_relu(X @ W^T + b)
// 128x256 tile, BK=32 double-buffered smem, 256 threads, 8x16 micro-tile.
// ---------------------------------------------------------------------------
__global__ __launch_bounds__(256, 1) void gemm_kernel(const float* __restrict__ X,
                                                      const float* __restrict__ W,
                                                      const float* __restrict__ bias) {
    extern __shared__ float sm[];
    float* sA = sm;              // [2][BK][PAD_A]
    float* sB = sm + 2 * BK * PAD_A;  // [2][BK][PAD_B]
#define ASM(b, kk, m) sA[(b) * (BK * PAD_A) + (kk) * PAD_A + (m)]
#define BSM(b, kk, n) sB[(b) * (BK * PAD_B) + (kk) * PAD_B + (n)]

    const int tid = threadIdx.x;
    const int tx = tid & 15;          // n group (16 groups)
    const int ty = tid >> 4;          // m group (16 groups of 8 rows)
    const int m0 = blockIdx.y * BM;
    const int n0 = blockIdx.x * BN;
    const int lk = (tid & 3) * 4;     // k offset 0/4/8/12
    const int lr = tid >> 2;          // row 0..63

    const float* Xb = X + (size_t)(m0 + lr) * D_IN + lk;
    const float* Wb = W + (size_t)(n0 + lr) * D_IN + lk;

    // accumulators: acc2[i][2g+h] = n pair (n0 + 64g + tx*4 + 2h .. +1), m = ty*8+i
    unsigned long long acc2[8][8];
#pragma unroll
    for (int i = 0; i < 8; i++)
#pragma unroll
        for (int p = 0; p < 8; p++) acc2[i][p] = 0ull;

    float4 ra[4];   // A: (pa, ka) in {0,1}^2
    float4 rb[8];   // B: (pb 0..3, kb 0..1)

    // load k-tile 0
#pragma unroll
    for (int pa = 0; pa < 2; pa++)
#pragma unroll
        for (int ka = 0; ka < 2; ka++)
            ra[pa * 2 + ka] = *(const float4*)(Xb + (size_t)(64 * pa) * D_IN + 16 * ka);
#pragma unroll
    for (int pb = 0; pb < 4; pb++)
#pragma unroll
        for (int kb = 0; kb < 2; kb++)
            rb[pb * 2 + kb] = *(const float4*)(Wb + (size_t)(64 * pb) * D_IN + 16 * kb);

    // store tile 0 into buffer 0
#pragma unroll
    for (int pa = 0; pa < 2; pa++)
#pragma unroll
        for (int ka = 0; ka < 2; ka++) {
            const float4 v = ra[pa * 2 + ka];
            const int kk = lk + 16 * ka;
            const int m = lr + 64 * pa;
            ASM(0, kk + 0, m) = v.x;
            ASM(0, kk + 1, m) = v.y;
            ASM(0, kk + 2, m) = v.z;
            ASM(0, kk + 3, m) = v.w;
        }
#pragma unroll
    for (int pb = 0; pb < 4; pb++)
#pragma unroll
        for (int kb = 0; kb < 2; kb++) {
            const float4 v = rb[pb * 2 + kb];
            const int kk = lk + 16 * kb;
            const int n = lr + 64 * pb;
            BSM(0, kk + 0, n) = v.x;
            BSM(0, kk + 1, n) = v.y;
            BSM(0, kk + 2, n) = v.z;
            BSM(0, kk + 3, n) = v.w;
        }
    __syncthreads();

    const int NT = D_IN / BK;   // 32 k-tiles
    for (int kt = 0; kt < NT; kt++) {
        const int cur = kt & 1;
        const bool more = (kt + 1 < NT);

        // prefetch next k-tile from global
        if (more) {
            const int k0 = (kt + 1) * BK;
#pragma unroll
            for (int pa = 0; pa < 2; pa++)
#pragma unroll
                for (int ka = 0; ka < 2; ka++)
                    ra[pa * 2 + ka] = *(const float4*)(Xb + (size_t)(64 * pa) * D_IN + k0 + 16 * ka);
#pragma unroll
            for (int pb = 0; pb < 4; pb++)
#pragma unroll
                for (int kb = 0; kb < 2; kb++)
                    rb[pb * 2 + kb] = *(const float4*)(Wb + (size_t)(64 * pb) * D_IN + k0 + 16 * kb);
        }

        // compute on buffer cur
#pragma unroll 8
        for (int kk = 0; kk < BK; kk++) {
            const float4 a0 = *(const float4*)&ASM(cur, kk, ty * 8);
            const float4 a1 = *(const float4*)&ASM(cur, kk, ty * 8 + 4);
            unsigned long long ad[8];
            ad[0] = dupf(a0.x); ad[1] = dupf(a0.y); ad[2] = dupf(a0.z); ad[3] = dupf(a0.w);
            ad[4] = dupf(a1.x); ad[5] = dupf(a1.y); ad[6] = dupf(a1.z); ad[7] = dupf(a1.w);
            ulonglong2 bg[4];
#pragma unroll
            for (int g = 0; g < 4; g++)
                bg[g] = *(const ulonglong2*)&BSM(cur, kk, 64 * g + tx * 4);
#pragma unroll
            for (int i = 0; i < 8; i++) {
#pragma unroll
                for (int g = 0; g < 4; g++) {
                    acc2[i][2 * g + 0] = ffma2(ad[i], bg[g].x, acc2[i][2 * g + 0]);
                    acc2[i][2 * g + 1] = ffma2(ad[i], bg[g].y, acc2[i][2 * g + 1]);
                }
            }
        }

        // store prefetched tile into the other buffer
        if (more) {
            const int nb = 1 - cur;
#pragma unroll
            for (int pa = 0; pa < 2; pa++)
#pragma unroll
                for (int ka = 0; ka < 2; ka++) {
                    const float4 v = ra[pa * 2 + ka];
                    const int kk = lk + 16 * ka;
                    const int m = lr + 64 * pa;
                    ASM(nb, kk + 0, m) = v.x;
                    ASM(nb, kk + 1, m) = v.y;
                    ASM(nb, kk + 2, m) = v.z;
                    ASM(nb, kk + 3, m) = v.w;
                }
#pragma unroll
            for (int pb = 0; pb < 4; pb++)
#pragma unroll
                for (int kb = 0; kb < 2; kb++) {
                    const float4 v = rb[pb * 2 + kb];
                    const int kk = lk + 16 * kb;
                    const int n = lr + 64 * pb;
                    BSM(nb, kk + 0, n) = v.x;
                    BSM(nb, kk + 1, n) = v.y;
                    BSM(nb, kk + 2, n) = v.z;
                    BSM(nb, kk + 3, n) = v.w;
                }
            __syncthreads();
        }
    }

    // epilogue: bias + leaky_relu, store
#pragma unroll
    for (int i = 0; i < 8; i++) {
        const int m = m0 + ty * 8 + i;
#pragma unroll
        for (int g = 0; g < 4; g++) {
            const float4 bv = *(const float4*)&bias[n0 + 64 * g + tx * 4];
            float f0, f1, f2, f3;
            unpack2(acc2[i][2 * g + 0], f0, f1);
            unpack2(acc2[i][2 * g + 1], f2, f3);
            float4 o;
            float v;
            v = f0 + bv.x; o.x = (v >= 0.f) ? v : NEG_SLOPE * v;
            v = f1 + bv.y; o.y = (v >= 0.f) ? v : NEG_SLOPE * v;
            v = f2 + bv.z; o.z = (v >= 0.f) ? v : NEG_SLOPE * v;
            v = f3 + bv.w; o.w = (v >= 0.f) ? v : NEG_SLOPE * v;
            *(float4*)&g_h[(size_t)m * D_OUT + n0 + 64 * g + tx * 4] = o;
        }
    }
#undef ASM
#undef BSM
}

// ---------------------------------------------------------------------------
// Phase 1b: per-row exact sorted top-128 (2-level radix select + bitonic)
// ---------------------------------------------------------------------------
__device__ __forceinline__ unsigned f2k(float f) {
    unsigned u = __float_as_uint(f);
    return (u & 0x80000000u) ? ~u : (u | 0x80000000u);
}
__device__ __forceinline__ float k2f(unsigned k) {
    unsigned u = (k & 0x80000000u) ? (k ^ 0x80000000u) : ~k;
    return __uint_as_float(u);
}

__global__ __launch_bounds__(256) void topc_kernel() {
    __shared__ unsigned skey[D_OUT];
    __shared__ int hist[256];
    __shared__ unsigned long long buf[256];
    __shared__ int s_b1, s_above1, s_b2, s_cnt;
    const int tid = threadIdx.x;
    const int row = blockIdx.x;

    const float4* src = (const float4*)(g_h + (size_t)row * D_OUT);
    for (int j = tid; j < D_OUT / 4; j += 256) {
        float4 v = src[j];
        skey[j * 4 + 0] = f2k(v.x);
        skey[j * 4 + 1] = f2k(v.y);
        skey[j * 4 + 2] = f2k(v.z);
        skey[j * 4 + 3] = f2k(v.w);
    }
    hist[tid] = 0;
    __syncthreads();

    for (int j = tid; j < D_OUT; j += 256) atomicAdd(&hist[skey[j] >> 24], 1);
    __syncthreads();
    if (tid == 0) {
        int A = 0, b;
        for (b = 255; b >= 0; b--) {
            if (A + hist[b] >= TOPC) break;
            A += hist[b];
        }
        s_b1 = b;
        s_above1 = A;
    }
    __syncthreads();
    const int b1 = s_b1;
    const int above1 = s_above1;

    hist[tid] = 0;
    __syncthreads();
    for (int j = tid; j < D_OUT; j += 256) {
        unsigned k = skey[j];
        if ((int)(k >> 24) == b1) atomicAdd(&hist[(k >> 16) & 255], 1);
    }
    __syncthreads();
    if (tid == 0) {
        int A = above1, b;
        for (b = 255; b >= 0; b--) {
            if (A + hist[b] >= TOPC) break;
            A += hist[b];
        }
        s_b2 = b;
        s_cnt = 0;
    }
    __syncthreads();
    const unsigned thr16 = ((unsigned)b1 << 8) | (unsigned)s_b2;

    for (int j = tid; j < D_OUT; j += 256) {
        unsigned k = skey[j];
        if ((k >> 16) >= thr16) {
            int slot = atomicAdd(&s_cnt, 1);
            if (slot < 256)
                buf[slot] = ((unsigned long long)k << 32) | (unsigned)j;
        }
    }
    __syncthreads();
    int c = s_cnt < 256 ? s_cnt : 256;
    if (tid >= c) buf[tid] = 0ull;
    __syncthreads();

    for (int k2 = 2; k2 <= 256; k2 <<= 1) {
        for (int j = k2 >> 1; j > 0; j >>= 1) {
            int ixj = tid ^ j;
            if (ixj > tid) {
                unsigned long long a = buf[tid], b = buf[ixj];
                bool desc = ((tid & k2) == 0);
                if (desc ? (a < b) : (a > b)) {
                    buf[tid] = b;
                    buf[ixj] = a;
                }
            }
            __syncthreads();
        }
    }

    if (tid < TOPC) {
        unsigned long long e = buf[tid];
        uint2 o;
        o.x = __float_as_uint(k2f((unsigned)(e >> 32)));
        o.y = (unsigned)(e & 0xffffffffu);
        g_cand[(size_t)row * TOPC + tid] = o;
    }
}

// ---------------------------------------------------------------------------
// Phase 2: serial scan (single warp)
// ---------------------------------------------------------------------------
__device__ __forceinline__ void warp_argmax(float& m, int& mi) {
#pragma unroll
    for (int off = 16; off; off >>= 1) {
        float om = __shfl_xor_sync(0xffffffffu, m, off);
        int oi = __shfl_xor_sync(0xffffffffu, mi, off);
        if (om > m || (om == m && oi < mi)) { m = om; mi = oi; }
    }
}

__device__ __noinline__ void slow_row(int row, int lane, int* lastSel,
                                      const float* phiTab, float* out) {
    const uint2* cr = g_cand + (size_t)row * TOPC;
    float sv[4];
    int si[4];
    int undCnt = 0;
    float lastVal = 0.f;
#pragma unroll
    for (int q = 0; q < 4; q++) {
        uint2 c = cr[q * 32 + lane];
        float val = __uint_as_float(c.x);
        int idx = (int)c.y;
        int t = row - lastSel[idx] - 1;
        t = t > 63 ? 63 : t;
        float phi = phiTab[t];
        sv[q] = val * phi;
        si[q] = idx;
        undCnt += (phi == 1.0f) ? 1 : 0;
        if (q == 3) lastVal = val;
    }
    float minv = __shfl_sync(0xffffffffu, lastVal, 31);
    int undTot = (int)__reduce_add_sync(0xffffffffu, (unsigned)undCnt);
    bool valid = (undTot >= 10) || (minv <= 0.0f);
    if (valid) {
        for (int it = 0; it < 10; it++) {
            float m = sv[0];
            int mq = 0;
#pragma unroll
            for (int q = 1; q < 4; q++)
                if (sv[q] > m) { m = sv[q]; mq = q; }
            int code = lane * 4 + mq;
            warp_argmax(m, code);
            if (m <= 0.0f) break;
            if (lane == (code >> 2)) {
                int q = code & 3;
                int idx = si[q];
                out[(size_t)row * D_OUT + idx] = 1.0f;
                lastSel[idx] = row;
                sv[q] = -3.0e38f;
            }
            __syncwarp();
        }
    } else {
        const float* hRow = g_h + (size_t)row * D_OUT;
        for (int it = 0; it < 10; it++) {
            float m = -3.0e38f;
            int mi = 0x7fffffff;
            for (int j = lane; j < D_OUT; j += 32) {
                int ls = lastSel[j];
                if (ls == row) continue;
                int t = row - ls - 1;
                t = t > 63 ? 63 : t;
                float s = hRow[j] * phiTab[t];
                if (s > m) { m = s; mi = j; }
            }
            warp_argmax(m, mi);
            if (m <= 0.0f) break;
            if (lane == 0) {
                out[(size_t)row * D_OUT + mi] = 1.0f;
                lastSel[mi] = row;
            }
            __syncwarp();
        }
    }
}

__device__ __forceinline__ void process_row(int row, uint2 cur, int lane,
                                            int* lastSel, const float* phiTab,
                                            float* out) {
    float val = __uint_as_float(cur.x);
    int idx = (int)cur.y;
    int ls = lastSel[idx];
    int t = row - ls - 1;
    t = t > 63 ? 63 : t;
    float phi = phiTab[t];
    float s = val * phi;
    bool und = (phi == 1.0f);
    unsigned bal = __ballot_sync(0xffffffffu, und);
    int p = -1;
    if (__popc(bal) >= 10) {
        unsigned b = bal;
#pragma unroll
        for (int i = 0; i < 9; i++) b &= b - 1;
        p = __ffs(b) - 1;
    }
    if (p >= 0) {
        int rank = 0;
        for (int j = 0; j <= p; j++) {
            float sj = __shfl_sync(0xffffffffu, s, j);
            rank += (sj > s) ? 1 : 0;
        }
        bool kept = (lane <= p) && (rank < 10) && (s > 0.0f);
        if (kept) {
            out[(size_t)row * D_OUT + idx] = 1.0f;
            lastSel[idx] = row;
        }
    } else {
        slow_row(row, lane, lastSel, phiTab, out);
    }
    __syncwarp();
}

__global__ void scan_kernel(float* __restrict__ out) {
    __shared__ int lastSel[D_OUT];
    __shared__ float phiTab[64];
    const int lane = threadIdx.x;

    for (int j = lane; j < D_OUT; j += 32) lastSel[j] = -1000;
    if (lane == 0) {
        float p = 0.f;
        phiTab[0] = 0.f;
        for (int t = 1; t < 64; t++) {
            if (p < 1.f) p = fminf(p + GAMMA, 1.f);
            phiTab[t] = p;
        }
    }
    __syncwarp();

    uint2 c0 = g_cand[(size_t)0 * TOPC + lane];
    uint2 c1 = g_cand[(size_t)1 * TOPC + lane];
    uint2 c2 = g_cand[(size_t)2 * TOPC + lane];

    for (int row = 0; row < N_ROWS; row += 3) {
        {
            uint2 cur = c0;
            int nr = row + 3 < N_ROWS ? row + 3 : N_ROWS - 1;
            c0 = g_cand[(size_t)nr * TOPC + lane];
            process_row(row, cur, lane, lastSel, phiTab, out);
        }
        if (row + 1 < N_ROWS) {
            uint2 cur = c1;
            int nr = row + 4 < N_ROWS ? row + 4 : N_ROWS - 1;
            c1 = g_cand[(size_t)nr * TOPC + lane];
            process_row(row + 1, cur, lane, lastSel, phiTab, out);
        }
        if (row + 2 < N_ROWS) {
            uint2 cur = c2;
            int nr = row + 5 < N_ROWS ? row + 5 : N_ROWS - 1;
            c2 = g_cand[(size_t)nr * TOPC + lane];
            process_row(row + 2, cur, lane, lastSel, phiTab, out);
        }
    }
}

// ---------------------------------------------------------------------------
extern "C" void kernel_launch(void* const* d_in, const int* in_sizes, int n_in,
                              void* d_out, int out_size) {
    const float* X = (const float*)d_in[0];
    const float* W = (const float*)d_in[1];
    const float* b = (const float*)d_in[2];
    float* out = (float*)d_out;

    cudaFuncSetAttribute(gemm_kernel, cudaFuncAttributeMaxDynamicSharedMemorySize,
                         SMEM_BYTES);

    int n4 = N_ROWS * D_OUT / 4;
    fill_kernel<<<(n4 + 255) / 256, 256>>>((float4*)out, n4);

    dim3 ggrid(D_OUT / BN, N_ROWS / BM);
    gemm_kernel<<<ggrid, 256, SMEM_BYTES>>>(X, W, b);

    topc_kernel<<<N_ROWS, 256>>>();

    scan_kernel<<<1, 32>>>(out);
}